// round 5
// baseline (speedup 1.0000x reference)
#include <cuda_runtime.h>

#define NC   21
#define NC2  (NC * NC)
#define NB   8
#define HW   (512 * 512)
#define Q    (HW / 4)              // float4 groups per channel plane (65536)
#define NBLOCKS ((NB * Q) / 128)   // 128 pixel-groups per block -> 4096 blocks

// Scratch: per-sample confusion matrices conf[b][true][pred].
// Zero at module load; the last block of each invocation re-zeroes after use.
__device__ int g_conf[NB * NC2];
__device__ unsigned int g_done;    // zero-init; reset by last block each run

__global__ void __launch_bounds__(256, 6)
conf_kernel(const float* __restrict__ pred,
            const float* __restrict__ tgt,
            float* __restrict__ out) {
    __shared__ int sconf[NC2];
    for (int i = threadIdx.x; i < NC2; i += blockDim.x) sconf[i] = 0;
    __syncthreads();

    const int lane   = threadIdx.x & 31;
    const int warpid = threadIdx.x >> 5;
    const bool lo    = (lane < 16);

    // Each warp covers 16 consecutive float4 pixel-groups; both half-warps
    // cover the SAME groups (lo half reads pred, hi half reads tgt).
    int gidx = (blockIdx.x * 8 + warpid) * 16 + (lane & 15);  // < NB*Q
    int b = gidx >> 16;            // Q = 65536; uniform within a block
    int p = gidx & (Q - 1);

    const float* src = lo ? pred : tgt;
    const float4* sp = reinterpret_cast<const float4*>(src) + (size_t)b * NC * Q + p;

    float4 m = __ldcs(sp);
    int ax = 0, ay = 0, az = 0, aw = 0;

    #pragma unroll
    for (int c = 1; c < NC; c++) {
        float4 v = __ldcs(sp + (size_t)c * Q);
        if (v.x > m.x) { m.x = v.x; ax = c; }
        if (v.y > m.y) { m.y = v.y; ay = c; }
        if (v.z > m.z) { m.z = v.z; az = c; }
        if (v.w > m.w) { m.w = v.w; aw = c; }
    }

    unsigned packed = (unsigned)ax | ((unsigned)ay << 8) |
                      ((unsigned)az << 16) | ((unsigned)aw << 24);
    unsigned other = __shfl_xor_sync(0xffffffffu, packed, 16);

    unsigned pidx = lo ? packed : other;   // pred argmaxes for this group
    unsigned tidx = lo ? other  : packed;  // tgt  argmaxes for this group

    // Split the 4 pixels between the two partner lanes: lo half commits
    // bytes 0,1; hi half commits bytes 2,3. No duplicates.
    int shift = lo ? 0 : 16;
    unsigned p0 = (pidx >> shift) & 0xff, t0 = (tidx >> shift) & 0xff;
    unsigned p1 = (pidx >> (shift + 8)) & 0xff, t1 = (tidx >> (shift + 8)) & 0xff;
    atomicAdd(&sconf[t0 * NC + p0], 1);
    atomicAdd(&sconf[t1 * NC + p1], 1);

    __syncthreads();
    for (int i = threadIdx.x; i < NC2; i += blockDim.x) {
        int v = sconf[i];
        if (v) atomicAdd(&g_conf[b * NC2 + i], v);
    }

    // ---- last-block finalize ----
    __threadfence();
    __shared__ unsigned int s_rank;
    if (threadIdx.x == 0) s_rank = atomicAdd(&g_done, 1u);
    __syncthreads();
    if (s_rank != NBLOCKS - 1) return;

    __shared__ float iou_sum[NB];
    __shared__ int   valid_cnt[NB];
    int t = threadIdx.x;
    if (t < NB) { iou_sum[t] = 0.0f; valid_cnt[t] = 0; }
    if (t == 0) g_done = 0;                 // reset for next invocation
    __syncthreads();

    if (t < NB * NC) {
        int bb = t / NC;
        int c  = t - bb * NC;
        const int* cb = &g_conf[bb * NC2];
        int tpv = __ldcg(&cb[c * NC + c]);
        int row = 0, col = 0;
        #pragma unroll
        for (int k = 0; k < NC; k++) {
            row += __ldcg(&cb[c * NC + k]);   // TP + FN
            col += __ldcg(&cb[k * NC + c]);   // TP + FP
        }
        if (tpv > 0) {
            float iou = (float)tpv / (float)(row + col - tpv);
            atomicAdd(&iou_sum[bb], iou);
            atomicAdd(&valid_cnt[bb], 1);
        }
    }
    __syncthreads();

    // Re-zero scratch for the next invocation (all reads done above).
    for (int i = t; i < NB * NC2; i += blockDim.x) g_conf[i] = 0;

    if (t == 0) {
        float s = 0.0f;
        #pragma unroll
        for (int bb = 0; bb < NB; bb++)
            s += iou_sum[bb] / fmaxf((float)valid_cnt[bb], 1.0f);
        out[0] = s / (float)NB;
    }
}

extern "C" void kernel_launch(void* const* d_in, const int* in_sizes, int n_in,
                              void* d_out, int out_size) {
    const float* pred = (const float*)d_in[0];
    const float* tgt  = (const float*)d_in[1];
    float* out = (float*)d_out;

    conf_kernel<<<NBLOCKS, 256>>>(pred, tgt, out);
}